// round 3
// baseline (speedup 1.0000x reference)
#include <cuda_runtime.h>
#include <math.h>

#define TT 256
#define DD 2048
#define NH 16
#define HDIM 128
#define NE 64
#define TOPK 8
#define DFF 1024
#define EPSF 1e-5f
#define ASCALE 0.08838834764831845f
#define NEGINF -3.4028234663852886e38f

// ---------------- scratch (device globals: alloc-free) ----------------
__device__ float g_xn[TT*DD];
__device__ float g_qb[TT*DD];
__device__ float g_kb[TT*DD];
__device__ float g_vb[TT*DD];
__device__ float g_sc[NH*TT*TT];
__device__ float g_ctx[TT*DD];
__device__ float g_x2[TT*DD];
__device__ float g_x3[TT*DD];
__device__ float g_act[(size_t)NE*256*DFF];
__device__ int   g_cnt[NE];
__device__ int   g_tok[NE*256];
__device__ float g_wgt[NE*256];

// ---------------- RMSNorm: one block per row ----------------
__global__ void rms_kernel(const float* __restrict__ in, const float* __restrict__ w,
                           float* __restrict__ out)
{
    int row = blockIdx.x;
    const float* xr = in + (size_t)row * DD;
    float ss = 0.f;
    for (int i = threadIdx.x; i < DD; i += 256) { float v = xr[i]; ss += v * v; }
    __shared__ float red[256];
    red[threadIdx.x] = ss; __syncthreads();
    for (int s = 128; s > 0; s >>= 1) {
        if (threadIdx.x < s) red[threadIdx.x] += red[threadIdx.x + s];
        __syncthreads();
    }
    float r = rsqrtf(red[0] / (float)DD + EPSF);
    for (int i = threadIdx.x; i < DD; i += 256)
        out[(size_t)row * DD + i] = xr[i] * r * w[i];
}

// ---------------- RoPE in place on q,k ([T, H*HD] layout) ----------------
__global__ void rope_kernel(float* __restrict__ q, float* __restrict__ k)
{
    int t = blockIdx.x / NH, h = blockIdx.x % NH;
    int i = threadIdx.x; // 64
    float inv = __expf(-((float)i / 64.0f) * 9.210340371976184f); // 10000^(-i/64)
    float ang = (float)t * inv;
    float c = cosf(ang), s = sinf(ang);
    int base = t * DD + h * HDIM;
    float q1 = q[base + i], q2 = q[base + 64 + i];
    q[base + i]      = q1 * c - q2 * s;
    q[base + 64 + i] = q1 * s + q2 * c;
    float k1 = k[base + i], k2 = k[base + 64 + i];
    k[base + i]      = k1 * c - k2 * s;
    k[base + 64 + i] = k1 * s + k2 * c;
}

// ---------------- softmax over rows of 256 (in place) ----------------
__global__ void softmax_kernel(float* __restrict__ s)
{
    int row = blockIdx.x;
    float* p = s + (size_t)row * TT;
    int i = threadIdx.x;
    float v = p[i];
    __shared__ float red[256];
    red[i] = v; __syncthreads();
    for (int st = 128; st > 0; st >>= 1) {
        if (i < st) red[i] = fmaxf(red[i], red[i + st]);
        __syncthreads();
    }
    float m = red[0]; __syncthreads();
    float e = expf(v - m);
    red[i] = e; __syncthreads();
    for (int st = 128; st > 0; st >>= 1) {
        if (i < st) red[i] += red[i + st];
        __syncthreads();
    }
    p[i] = e / red[0];
}

__global__ void zero_cnt_kernel(int* cnt)
{
    if (threadIdx.x < NE) cnt[threadIdx.x] = 0;
}

// ---------------- router: logits, softmax, top-8, scatter ----------------
__global__ void router_kernel(const float* __restrict__ x3, const float* __restrict__ gw,
                              int* __restrict__ cnt, int* __restrict__ tok, float* __restrict__ wgt)
{
    int t = blockIdx.x;
    __shared__ float xr[DD];
    __shared__ float lg[NE];
    for (int i = threadIdx.x; i < DD; i += blockDim.x) xr[i] = x3[(size_t)t * DD + i];
    __syncthreads();
    if (threadIdx.x < NE) {
        const float* wrow = gw + (size_t)threadIdx.x * DD;
        float acc = 0.f;
        for (int j = 0; j < DD; j++) acc += xr[j] * wrow[j];
        lg[threadIdx.x] = acc;
    }
    __syncthreads();
    if (threadIdx.x == 0) {
        float mx = -1e30f;
        for (int e = 0; e < NE; e++) mx = fmaxf(mx, lg[e]);
        float sum = 0.f;
        for (int e = 0; e < NE; e++) { lg[e] = expf(lg[e] - mx); sum += lg[e]; }
        bool used[NE];
        for (int e = 0; e < NE; e++) used[e] = false;
        for (int s = 0; s < TOPK; s++) {
            int bi = 0; float bv = -1.f;
            for (int e = 0; e < NE; e++)
                if (!used[e] && lg[e] > bv) { bv = lg[e]; bi = e; }
            used[bi] = true;
            int pos = atomicAdd(&cnt[bi], 1);
            tok[bi * 256 + pos] = t;
            wgt[bi * 256 + pos] = bv / sum;
        }
    }
}

// ====================================================================
// Double-buffered NT GEMM core: C[M,N] = alpha*A[M,K]@B[N,K]^T (+res)
// 256 threads; BM x BN tile; BK=16; thread tile TM x TN (TM in {2,4}, TN in {4,8}).
// ====================================================================
template<int BM, int BN, int TM, int TN>
__device__ __forceinline__ void gemm_nt_core(
    const float* __restrict__ A, int lda,
    const float* __restrict__ B, int ldb,
    float* __restrict__ C, int ldc, int K,
    const float* __restrict__ res, float alpha, bool causal,
    float* __restrict__ C2)
{
    constexpr int BK = 16;
    constexpr int AF = (BM * BK) / (4 * 256);
    constexpr int BF = (BN * BK) / (4 * 256);
    __shared__ float As[2][BK][BM];
    __shared__ float Bs[2][BK][BN];
    const int bm = blockIdx.y * BM, bn = blockIdx.x * BN;
    const int tid = threadIdx.x;
    const int ty = tid >> 4, tx = tid & 15;

    float4 pa[AF], pb[BF];
    float acc[TM][TN];
#pragma unroll
    for (int i = 0; i < TM; i++)
#pragma unroll
        for (int j = 0; j < TN; j++) acc[i][j] = 0.f;

    const int NK = K / BK;

    // prologue: tile 0
#pragma unroll
    for (int i = 0; i < AF; i++) { int idx = tid + i * 256; int r = idx >> 2, c = idx & 3;
        pa[i] = *(const float4*)(A + (size_t)(bm + r) * lda + c * 4); }
#pragma unroll
    for (int i = 0; i < BF; i++) { int idx = tid + i * 256; int r = idx >> 2, c = idx & 3;
        pb[i] = *(const float4*)(B + (size_t)(bn + r) * ldb + c * 4); }
#pragma unroll
    for (int i = 0; i < AF; i++) { int idx = tid + i * 256; int r = idx >> 2, c = idx & 3;
        As[0][c*4+0][r] = pa[i].x; As[0][c*4+1][r] = pa[i].y;
        As[0][c*4+2][r] = pa[i].z; As[0][c*4+3][r] = pa[i].w; }
#pragma unroll
    for (int i = 0; i < BF; i++) { int idx = tid + i * 256; int r = idx >> 2, c = idx & 3;
        Bs[0][c*4+0][r] = pb[i].x; Bs[0][c*4+1][r] = pb[i].y;
        Bs[0][c*4+2][r] = pb[i].z; Bs[0][c*4+3][r] = pb[i].w; }
    __syncthreads();

    for (int kt = 0; kt < NK; kt++) {
        const int cur = kt & 1;
        if (kt + 1 < NK) {
            const int k0 = (kt + 1) * BK;
#pragma unroll
            for (int i = 0; i < AF; i++) { int idx = tid + i * 256; int r = idx >> 2, c = idx & 3;
                pa[i] = *(const float4*)(A + (size_t)(bm + r) * lda + k0 + c * 4); }
#pragma unroll
            for (int i = 0; i < BF; i++) { int idx = tid + i * 256; int r = idx >> 2, c = idx & 3;
                pb[i] = *(const float4*)(B + (size_t)(bn + r) * ldb + k0 + c * 4); }
        }
#pragma unroll
        for (int kk = 0; kk < BK; kk++) {
            float ar[TM], br[TN];
            if constexpr (TM == 4) {
                float4 v = *(const float4*)&As[cur][kk][ty * 4];
                ar[0] = v.x; ar[1] = v.y; ar[2] = v.z; ar[3] = v.w;
            } else {
                float2 v = *(const float2*)&As[cur][kk][ty * 2];
                ar[0] = v.x; ar[1] = v.y;
            }
            if constexpr (TN == 8) {
                float4 v0 = *(const float4*)&Bs[cur][kk][tx * 8];
                float4 v1 = *(const float4*)&Bs[cur][kk][tx * 8 + 4];
                br[0] = v0.x; br[1] = v0.y; br[2] = v0.z; br[3] = v0.w;
                br[4] = v1.x; br[5] = v1.y; br[6] = v1.z; br[7] = v1.w;
            } else {
                float4 v0 = *(const float4*)&Bs[cur][kk][tx * 4];
                br[0] = v0.x; br[1] = v0.y; br[2] = v0.z; br[3] = v0.w;
            }
#pragma unroll
            for (int i = 0; i < TM; i++)
#pragma unroll
                for (int j = 0; j < TN; j++) acc[i][j] += ar[i] * br[j];
        }
        if (kt + 1 < NK) {
            const int nxt = cur ^ 1;
#pragma unroll
            for (int i = 0; i < AF; i++) { int idx = tid + i * 256; int r = idx >> 2, c = idx & 3;
                As[nxt][c*4+0][r] = pa[i].x; As[nxt][c*4+1][r] = pa[i].y;
                As[nxt][c*4+2][r] = pa[i].z; As[nxt][c*4+3][r] = pa[i].w; }
#pragma unroll
            for (int i = 0; i < BF; i++) { int idx = tid + i * 256; int r = idx >> 2, c = idx & 3;
                Bs[nxt][c*4+0][r] = pb[i].x; Bs[nxt][c*4+1][r] = pb[i].y;
                Bs[nxt][c*4+2][r] = pb[i].z; Bs[nxt][c*4+3][r] = pb[i].w; }
        }
        __syncthreads();
    }

#pragma unroll
    for (int i = 0; i < TM; i++) {
        const int row = bm + ty * TM + i;
#pragma unroll
        for (int j = 0; j < TN; j++) {
            const int col = bn + tx * TN + j;
            float v = acc[i][j] * alpha;
            if (causal && col > row) v = NEGINF;
            if (res) v += res[(size_t)row * ldc + col];
            C[(size_t)row * ldc + col] = v;
            if (C2) C2[(size_t)row * ldc + col] = v;
        }
    }
}

// ---------------- NN core (P@V): BM=64, BN=64, 4x4, double-buffered ----------------
__device__ __forceinline__ void gemm_nn_core(
    const float* __restrict__ A, int lda,
    const float* __restrict__ B, int ldb,
    float* __restrict__ C, int ldc, int K)
{
    constexpr int BK = 16;
    __shared__ float As[2][BK][64];
    __shared__ float Bs[2][BK][64];
    const int bm = blockIdx.y * 64, bn = blockIdx.x * 64;
    const int tid = threadIdx.x, ty = tid >> 4, tx = tid & 15;
    const int alr = tid >> 2, alc = tid & 3;   // A: 64 rows x 4 float4
    const int bkr = tid >> 4, bc4 = tid & 15;  // B: 16 k-rows x 16 float4
    float4 pa, pb;
    float acc[4][4];
#pragma unroll
    for (int i = 0; i < 4; i++)
#pragma unroll
        for (int j = 0; j < 4; j++) acc[i][j] = 0.f;
    const int NK = K / BK;

    pa = *(const float4*)(A + (size_t)(bm + alr) * lda + alc * 4);
    pb = *(const float4*)(B + (size_t)bkr * ldb + bn + bc4 * 4);
    As[0][alc*4+0][alr] = pa.x; As[0][alc*4+1][alr] = pa.y;
    As[0][alc*4+2][alr] = pa.z; As[0][alc*4+3][alr] = pa.w;
    *(float4*)&Bs[0][bkr][bc4 * 4] = pb;
    __syncthreads();

    for (int kt = 0; kt < NK; kt++) {
        const int cur = kt & 1;
        if (kt + 1 < NK) {
            const int k0 = (kt + 1) * BK;
            pa = *(const float4*)(A + (size_t)(bm + alr) * lda + k0 + alc * 4);
            pb = *(const float4*)(B + (size_t)(k0 + bkr) * ldb + bn + bc4 * 4);
        }
#pragma unroll
        for (int kk = 0; kk < BK; kk++) {
            float4 av = *(const float4*)&As[cur][kk][ty * 4];
            float4 bv = *(const float4*)&Bs[cur][kk][tx * 4];
            float ar[4] = {av.x, av.y, av.z, av.w};
            float br[4] = {bv.x, bv.y, bv.z, bv.w};
#pragma unroll
            for (int i = 0; i < 4; i++)
#pragma unroll
                for (int j = 0; j < 4; j++) acc[i][j] += ar[i] * br[j];
        }
        if (kt + 1 < NK) {
            const int nxt = cur ^ 1;
            As[nxt][alc*4+0][alr] = pa.x; As[nxt][alc*4+1][alr] = pa.y;
            As[nxt][alc*4+2][alr] = pa.z; As[nxt][alc*4+3][alr] = pa.w;
            *(float4*)&Bs[nxt][bkr][bc4 * 4] = pb;
        }
        __syncthreads();
    }
#pragma unroll
    for (int i = 0; i < 4; i++) {
        const int row = bm + ty * 4 + i;
#pragma unroll
        for (int j = 0; j < 4; j++)
            C[(size_t)row * ldc + bn + tx * 4 + j] = acc[i][j];
    }
}

// ---------------- wrapper kernels ----------------
__global__ void qkv_kernel(const float* __restrict__ xn,
                           const float* __restrict__ qw, const float* __restrict__ kw,
                           const float* __restrict__ vw,
                           float* __restrict__ qb, float* __restrict__ kb, float* __restrict__ vb)
{
    const float* B; float* C;
    if (blockIdx.z == 0)      { B = qw; C = qb; }
    else if (blockIdx.z == 1) { B = kw; C = kb; }
    else                      { B = vw; C = vb; }
    gemm_nt_core<64,128,4,8>(xn, DD, B, DD, C, DD, DD, nullptr, 1.f, false, nullptr);
}

__global__ void score_kernel(const float* __restrict__ q, const float* __restrict__ k,
                             float* __restrict__ sc)
{
    int h = blockIdx.z;
    gemm_nt_core<64,128,4,8>(q + h * HDIM, DD, k + h * HDIM, DD,
                             sc + (size_t)h * TT * TT, TT, HDIM,
                             nullptr, ASCALE, true, nullptr);
}

__global__ void pv_kernel(const float* __restrict__ sc, const float* __restrict__ v,
                          float* __restrict__ ctx)
{
    int h = blockIdx.z;
    gemm_nn_core(sc + (size_t)h * TT * TT, TT, v + h * HDIM, DD, ctx + h * HDIM, DD, TT);
}

__global__ void oproj_kernel(const float* __restrict__ ctx, const float* __restrict__ ow,
                             const float* __restrict__ x, float* __restrict__ x2,
                             float* __restrict__ out)
{
    gemm_nt_core<64,128,4,8>(ctx, DD, ow, DD, x2, DD, DD, x, 1.f, false, out);
}

// ---------------- MoE gate_up: BM=32, BN=128 (gate+up), double-buffered ----------------
__global__ void moe_gate_up(const float* __restrict__ x3, const float* __restrict__ w_gu,
                            const int* __restrict__ cnt, const int* __restrict__ tok,
                            const float* __restrict__ wgt, float* __restrict__ act)
{
    const int e = blockIdx.z;
    const int nt = cnt[e];
    const int m0 = blockIdx.y * 32;
    if (m0 >= nt) return;
    const int n0 = blockIdx.x * 128;
    __shared__ int stok[32];
    __shared__ float As[2][16][32];
    __shared__ float Bg[2][16][128];
    __shared__ float Bu[2][16][128];
    const int tid = threadIdx.x, ty = tid >> 4, tx = tid & 15;
    if (tid < 32) stok[tid] = tok[e * 256 + min(m0 + tid, nt - 1)];
    __syncthreads();
    const int alr = tid >> 3, alc = tid & 7;
    const float* arow = x3 + (size_t)stok[alr] * DD + alc * 2;
    const float* Wg = w_gu + (size_t)e * (2 * DFF) * DD;
    const float* Wu = Wg + (size_t)DFF * DD;

    float2 pa; float4 pg[2], pu[2];
    float ag[2][8], au[2][8];
#pragma unroll
    for (int i = 0; i < 2; i++)
#pragma unroll
        for (int j = 0; j < 8; j++) { ag[i][j] = 0.f; au[i][j] = 0.f; }

    const int NK = DD / 16;
    pa = *(const float2*)(arow);
#pragma unroll
    for (int i = 0; i < 2; i++) { int idx = tid + i * 256; int r = idx >> 2, c = idx & 3;
        pg[i] = *(const float4*)(Wg + (size_t)(n0 + r) * DD + c * 4);
        pu[i] = *(const float4*)(Wu + (size_t)(n0 + r) * DD + c * 4); }
    As[0][alc*2][alr] = pa.x; As[0][alc*2+1][alr] = pa.y;
#pragma unroll
    for (int i = 0; i < 2; i++) { int idx = tid + i * 256; int r = idx >> 2, c = idx & 3;
        Bg[0][c*4+0][r] = pg[i].x; Bg[0][c*4+1][r] = pg[i].y;
        Bg[0][c*4+2][r] = pg[i].z; Bg[0][c*4+3][r] = pg[i].w;
        Bu[0][c*4+0][r] = pu[i].x; Bu[0][c*4+1][r] = pu[i].y;
        Bu[0][c*4+2][r] = pu[i].z; Bu[0][c*4+3][r] = pu[i].w; }
    __syncthreads();

    for (int kt = 0; kt < NK; kt++) {
        const int cur = kt & 1;
        if (kt + 1 < NK) {
            const int k0 = (kt + 1) * 16;
            pa = *(const float2*)(arow + k0);
#pragma unroll
            for (int i = 0; i < 2; i++) { int idx = tid + i * 256; int r = idx >> 2, c = idx & 3;
                pg[i] = *(const float4*)(Wg + (size_t)(n0 + r) * DD + k0 + c * 4);
                pu[i] = *(const float4*)(Wu + (size_t)(n0 + r) * DD + k0 + c * 4); }
        }
#pragma unroll
        for (int kk = 0; kk < 16; kk++) {
            float2 av = *(const float2*)&As[cur][kk][ty * 2];
            float4 g0 = *(const float4*)&Bg[cur][kk][tx * 8];
            float4 g1 = *(const float4*)&Bg[cur][kk][tx * 8 + 4];
            float4 u0 = *(const float4*)&Bu[cur][kk][tx * 8];
            float4 u1 = *(const float4*)&Bu[cur][kk][tx * 8 + 4];
            float gr[8] = {g0.x, g0.y, g0.z, g0.w, g1.x, g1.y, g1.z, g1.w};
            float ur[8] = {u0.x, u0.y, u0.z, u0.w, u1.x, u1.y, u1.z, u1.w};
#pragma unroll
            for (int j = 0; j < 8; j++) {
                ag[0][j] += av.x * gr[j]; ag[1][j] += av.y * gr[j];
                au[0][j] += av.x * ur[j]; au[1][j] += av.y * ur[j];
            }
        }
        if (kt + 1 < NK) {
            const int nxt = cur ^ 1;
            As[nxt][alc*2][alr] = pa.x; As[nxt][alc*2+1][alr] = pa.y;
#pragma unroll
            for (int i = 0; i < 2; i++) { int idx = tid + i * 256; int r = idx >> 2, c = idx & 3;
                Bg[nxt][c*4+0][r] = pg[i].x; Bg[nxt][c*4+1][r] = pg[i].y;
                Bg[nxt][c*4+2][r] = pg[i].z; Bg[nxt][c*4+3][r] = pg[i].w;
                Bu[nxt][c*4+0][r] = pu[i].x; Bu[nxt][c*4+1][r] = pu[i].y;
                Bu[nxt][c*4+2][r] = pu[i].z; Bu[nxt][c*4+3][r] = pu[i].w; }
        }
        __syncthreads();
    }

#pragma unroll
    for (int i = 0; i < 2; i++) {
        const int r = ty * 2 + i;
        if (m0 + r < nt) {
            const float w = wgt[e * 256 + m0 + r];
            const size_t base = ((size_t)(e * 256 + m0 + r)) * DFF + n0 + tx * 8;
#pragma unroll
            for (int j = 0; j < 8; j++) {
                float g = ag[i][j];
                float sg = g / (1.f + expf(-g));
                act[base + j] = sg * au[i][j] * w;
            }
        }
    }
}

// ---------------- MoE down: BM=32, BN=128, NT, atomicAdd epilogue ----------------
__global__ void moe_down(const float* __restrict__ act, const float* __restrict__ w_down,
                         const int* __restrict__ cnt, const int* __restrict__ tok,
                         float* __restrict__ out)
{
    const int e = blockIdx.z;
    const int nt = cnt[e];
    const int m0 = blockIdx.y * 32;
    if (m0 >= nt) return;
    const int n0 = blockIdx.x * 128;
    __shared__ float As[2][16][32];
    __shared__ float Bs[2][16][128];
    const int tid = threadIdx.x, ty = tid >> 4, tx = tid & 15;
    const int alr = tid >> 3, alc = tid & 7;
    // rows beyond nt read in-bounds junk; their results are discarded in epilogue
    const float* arow = act + ((size_t)(e * 256 + m0 + alr)) * DFF + alc * 2;
    const float* W = w_down + (size_t)e * DD * DFF;

    float2 pa; float4 pb[2];
    float acc[2][8];
#pragma unroll
    for (int i = 0; i < 2; i++)
#pragma unroll
        for (int j = 0; j < 8; j++) acc[i][j] = 0.f;

    const int NK = DFF / 16;
    pa = *(const float2*)(arow);
#pragma unroll
    for (int i = 0; i < 2; i++) { int idx = tid + i * 256; int r = idx >> 2, c = idx & 3;
        pb[i] = *(const float4*)(W + (size_t)(n0 + r) * DFF + c * 4); }
    As[0][alc*2][alr] = pa.x; As[0][alc*2+1][alr] = pa.y;
#pragma unroll
    for (int i = 0; i < 2; i++) { int idx = tid + i * 256; int r = idx >> 2, c = idx & 3;
        Bs[0][c*4+0][r] = pb[i].x; Bs[0][c*4+1][r] = pb[i].y;
        Bs[0][c*4+2][r] = pb[i].z; Bs[0][c*4+3][r] = pb[i].w; }
    __syncthreads();

    for (int kt = 0; kt < NK; kt++) {
        const int cur = kt & 1;
        if (kt + 1 < NK) {
            const int k0 = (kt + 1) * 16;
            pa = *(const float2*)(arow + k0);
#pragma unroll
            for (int i = 0; i < 2; i++) { int idx = tid + i * 256; int r = idx >> 2, c = idx & 3;
                pb[i] = *(const float4*)(W + (size_t)(n0 + r) * DFF + k0 + c * 4); }
        }
#pragma unroll
        for (int kk = 0; kk < 16; kk++) {
            float2 av = *(const float2*)&As[cur][kk][ty * 2];
            float4 b0 = *(const float4*)&Bs[cur][kk][tx * 8];
            float4 b1 = *(const float4*)&Bs[cur][kk][tx * 8 + 4];
            float br[8] = {b0.x, b0.y, b0.z, b0.w, b1.x, b1.y, b1.z, b1.w};
#pragma unroll
            for (int j = 0; j < 8; j++) {
                acc[0][j] += av.x * br[j];
                acc[1][j] += av.y * br[j];
            }
        }
        if (kt + 1 < NK) {
            const int nxt = cur ^ 1;
            As[nxt][alc*2][alr] = pa.x; As[nxt][alc*2+1][alr] = pa.y;
#pragma unroll
            for (int i = 0; i < 2; i++) { int idx = tid + i * 256; int r = idx >> 2, c = idx & 3;
                Bs[nxt][c*4+0][r] = pb[i].x; Bs[nxt][c*4+1][r] = pb[i].y;
                Bs[nxt][c*4+2][r] = pb[i].z; Bs[nxt][c*4+3][r] = pb[i].w; }
        }
        __syncthreads();
    }

#pragma unroll
    for (int i = 0; i < 2; i++) {
        const int r = ty * 2 + i;
        if (m0 + r < nt) {
            const int t = tok[e * 256 + m0 + r];
#pragma unroll
            for (int j = 0; j < 8; j++)
                atomicAdd(&out[(size_t)t * DD + n0 + tx * 8 + j], acc[i][j]);
        }
    }
}

// ---------------- host launch ----------------
extern "C" void kernel_launch(void* const* d_in, const int* in_sizes, int n_in,
                              void* d_out, int out_size)
{
    const float* x    = (const float*)d_in[0];
    const float* ln1  = (const float*)d_in[1];
    const float* qw   = (const float*)d_in[2];
    const float* kw   = (const float*)d_in[3];
    const float* vw   = (const float*)d_in[4];
    const float* qn   = (const float*)d_in[5];
    const float* kn   = (const float*)d_in[6];
    const float* ow   = (const float*)d_in[7];
    const float* ln2  = (const float*)d_in[8];
    const float* gw   = (const float*)d_in[9];
    const float* guw  = (const float*)d_in[10];
    const float* dw   = (const float*)d_in[11];
    float* out = (float*)d_out;

    float *p_xn, *p_qb, *p_kb, *p_vb, *p_sc, *p_ctx, *p_x2, *p_x3, *p_act, *p_wgt;
    int *p_cnt, *p_tok;
    cudaGetSymbolAddress((void**)&p_xn,  g_xn);
    cudaGetSymbolAddress((void**)&p_qb,  g_qb);
    cudaGetSymbolAddress((void**)&p_kb,  g_kb);
    cudaGetSymbolAddress((void**)&p_vb,  g_vb);
    cudaGetSymbolAddress((void**)&p_sc,  g_sc);
    cudaGetSymbolAddress((void**)&p_ctx, g_ctx);
    cudaGetSymbolAddress((void**)&p_x2,  g_x2);
    cudaGetSymbolAddress((void**)&p_x3,  g_x3);
    cudaGetSymbolAddress((void**)&p_act, g_act);
    cudaGetSymbolAddress((void**)&p_cnt, g_cnt);
    cudaGetSymbolAddress((void**)&p_tok, g_tok);
    cudaGetSymbolAddress((void**)&p_wgt, g_wgt);

    // 1. xn = rms(x, ln1)
    rms_kernel<<<TT, 256>>>(x, ln1, p_xn);

    // 2. fused q/k/v projections (z selects weight)
    dim3 gqkv(DD / 128, TT / 64, 3);
    qkv_kernel<<<gqkv, 256>>>(p_xn, qw, kw, vw, p_qb, p_kb, p_vb);

    // 3. q/k RMS over full D
    rms_kernel<<<TT, 256>>>(p_qb, qn, p_qb);
    rms_kernel<<<TT, 256>>>(p_kb, kn, p_kb);

    // 4. RoPE
    rope_kernel<<<TT * NH, 64>>>(p_qb, p_kb);

    // 5. scores with causal mask
    dim3 gsc(TT / 128, TT / 64, NH);
    score_kernel<<<gsc, 256>>>(p_qb, p_kb, p_sc);

    // 6. softmax
    softmax_kernel<<<NH * TT, 256>>>(p_sc);

    // 7. ctx = P @ V
    dim3 gpv(HDIM / 64, TT / 64, NH);
    pv_kernel<<<gpv, 256>>>(p_sc, p_vb, p_ctx);

    // 8. x2 = x + ctx @ o_w^T  (also writes residual base into out)
    dim3 go(DD / 128, TT / 64, 1);
    oproj_kernel<<<go, 256>>>(p_ctx, ow, x, p_x2, out);

    // 9. x3 = rms(x2, ln2)
    rms_kernel<<<TT, 256>>>(p_x2, ln2, p_x3);

    // 10. router
    zero_cnt_kernel<<<1, 64>>>(p_cnt);
    router_kernel<<<TT, 256>>>(p_x3, gw, p_cnt, p_tok, p_wgt);

    // 11. grouped gate_up (+silu*up*weight)
    dim3 ggu(DFF / 128, 8, NE);
    moe_gate_up<<<ggu, 256>>>(p_x3, guw, p_cnt, p_tok, p_wgt, p_act);

    // 12. grouped down-proj, atomic accumulate
    dim3 gdn(DD / 128, 8, NE);
    moe_down<<<gdn, 256>>>(p_act, dw, p_cnt, p_tok, out);
}

// round 4
// speedup vs baseline: 3.2302x; 3.2302x over previous
#include <cuda_runtime.h>
#include <cuda_bf16.h>
#include <math.h>

#define TT 256
#define DD 2048
#define NH 16
#define HDIM 128
#define NE 64
#define TOPK 8
#define DFF 1024
#define EPSF 1e-5f
#define ASCALE 0.08838834764831845f
#define NEGINF -3.4028234663852886e38f

#define LW 24    // bf16 elements per smem tile row (16 data + 8 pad)
#define LWB 48   // bytes per row

// ---------------- scratch (device globals: alloc-free) ----------------
__device__ float g_xn[TT*DD];
__device__ float g_qb[TT*DD];
__device__ float g_kb[TT*DD];
__device__ float g_vb[TT*DD];
__device__ float g_sc[NH*TT*TT];
__device__ float g_ctx[TT*DD];
__device__ float g_x2[TT*DD];
__device__ float g_x3[TT*DD];
__device__ float g_act[(size_t)NE*256*DFF];
__device__ int   g_cnt[NE];
__device__ int   g_tok[NE*256];
__device__ float g_wgt[NE*256];

// ==================== PTX helpers ====================
__device__ __forceinline__ unsigned smem_u32(const void* p) {
    return (unsigned)__cvta_generic_to_shared(p);
}
__device__ __forceinline__ void ldmat_x4(unsigned addr, unsigned &r0, unsigned &r1,
                                         unsigned &r2, unsigned &r3) {
    asm volatile("ldmatrix.sync.aligned.m8n8.x4.shared.b16 {%0,%1,%2,%3}, [%4];"
        : "=r"(r0), "=r"(r1), "=r"(r2), "=r"(r3) : "r"(addr));
}
__device__ __forceinline__ void mma_bf16(float* c,
    unsigned a0, unsigned a1, unsigned a2, unsigned a3, unsigned b0, unsigned b1) {
    asm volatile("mma.sync.aligned.m16n8k16.row.col.f32.bf16.bf16.f32 "
        "{%0,%1,%2,%3}, {%4,%5,%6,%7}, {%8,%9}, {%0,%1,%2,%3};"
        : "+f"(c[0]), "+f"(c[1]), "+f"(c[2]), "+f"(c[3])
        : "r"(a0), "r"(a1), "r"(a2), "r"(a3), "r"(b0), "r"(b1));
}
// split two fp32 into packed bf16 hi pair + bf16 lo-residual pair (x0 -> low half)
__device__ __forceinline__ void split_pair(float x0, float x1, unsigned &h, unsigned &l) {
    asm("cvt.rn.bf16x2.f32 %0, %1, %2;" : "=r"(h) : "f"(x1), "f"(x0));
    float h0 = __uint_as_float(h << 16);
    float h1 = __uint_as_float(h & 0xffff0000u);
    float r0 = x0 - h0, r1 = x1 - h1;
    asm("cvt.rn.bf16x2.f32 %0, %1, %2;" : "=r"(l) : "f"(r1), "f"(r0));
}
__device__ __forceinline__ void cvt_store(float4 v, __nv_bfloat16* ph, __nv_bfloat16* pl) {
    unsigned h0, l0, h1, l1;
    split_pair(v.x, v.y, h0, l0);
    split_pair(v.z, v.w, h1, l1);
    *(uint2*)ph = make_uint2(h0, h1);
    *(uint2*)pl = make_uint2(l0, l1);
}

// ==================== small elementwise kernels (proven R2 versions) ====================
__global__ void rms_kernel(const float* __restrict__ in, const float* __restrict__ w,
                           float* __restrict__ out)
{
    int row = blockIdx.x;
    const float* xr = in + (size_t)row * DD;
    float ss = 0.f;
    for (int i = threadIdx.x; i < DD; i += 256) { float v = xr[i]; ss += v * v; }
    __shared__ float red[256];
    red[threadIdx.x] = ss; __syncthreads();
    for (int s = 128; s > 0; s >>= 1) {
        if (threadIdx.x < s) red[threadIdx.x] += red[threadIdx.x + s];
        __syncthreads();
    }
    float r = rsqrtf(red[0] / (float)DD + EPSF);
    for (int i = threadIdx.x; i < DD; i += 256)
        out[(size_t)row * DD + i] = xr[i] * r * w[i];
}

__global__ void rope_kernel(float* __restrict__ q, float* __restrict__ k)
{
    int t = blockIdx.x / NH, h = blockIdx.x % NH;
    int i = threadIdx.x;
    float inv = __expf(-((float)i / 64.0f) * 9.210340371976184f);
    float ang = (float)t * inv;
    float c = cosf(ang), s = sinf(ang);
    int base = t * DD + h * HDIM;
    float q1 = q[base + i], q2 = q[base + 64 + i];
    q[base + i]      = q1 * c - q2 * s;
    q[base + 64 + i] = q1 * s + q2 * c;
    float k1 = k[base + i], k2 = k[base + 64 + i];
    k[base + i]      = k1 * c - k2 * s;
    k[base + 64 + i] = k1 * s + k2 * c;
}

__global__ void softmax_kernel(float* __restrict__ s)
{
    int row = blockIdx.x;
    float* p = s + (size_t)row * TT;
    int i = threadIdx.x;
    float v = p[i];
    __shared__ float red[256];
    red[i] = v; __syncthreads();
    for (int st = 128; st > 0; st >>= 1) {
        if (i < st) red[i] = fmaxf(red[i], red[i + st]);
        __syncthreads();
    }
    float m = red[0]; __syncthreads();
    float e = expf(v - m);
    red[i] = e; __syncthreads();
    for (int st = 128; st > 0; st >>= 1) {
        if (i < st) red[i] += red[i + st];
        __syncthreads();
    }
    p[i] = e / red[0];
}

__global__ void zero_cnt_kernel(int* cnt)
{
    if (threadIdx.x < NE) cnt[threadIdx.x] = 0;
}

__global__ void router_kernel(const float* __restrict__ x3, const float* __restrict__ gw,
                              int* __restrict__ cnt, int* __restrict__ tok, float* __restrict__ wgt)
{
    int t = blockIdx.x;
    __shared__ float xr[DD];
    __shared__ float lg[NE];
    for (int i = threadIdx.x; i < DD; i += blockDim.x) xr[i] = x3[(size_t)t * DD + i];
    __syncthreads();
    if (threadIdx.x < NE) {
        const float* wrow = gw + (size_t)threadIdx.x * DD;
        float acc = 0.f;
        for (int j = 0; j < DD; j++) acc += xr[j] * wrow[j];
        lg[threadIdx.x] = acc;
    }
    __syncthreads();
    if (threadIdx.x == 0) {
        float mx = -1e30f;
        for (int e = 0; e < NE; e++) mx = fmaxf(mx, lg[e]);
        float sum = 0.f;
        for (int e = 0; e < NE; e++) { lg[e] = expf(lg[e] - mx); sum += lg[e]; }
        bool used[NE];
        for (int e = 0; e < NE; e++) used[e] = false;
        for (int s = 0; s < TOPK; s++) {
            int bi = 0; float bv = -1.f;
            for (int e = 0; e < NE; e++)
                if (!used[e] && lg[e] > bv) { bv = lg[e]; bi = e; }
            used[bi] = true;
            int pos = atomicAdd(&cnt[bi], 1);
            tok[bi * 256 + pos] = t;
            wgt[bi * 256 + pos] = bv / sum;
        }
    }
}

// ==================== SIMT fp32 GEMMs for attention (proven R1/R2) ====================
__global__ void score_gemm(const float* __restrict__ Q, const float* __restrict__ Kk,
                           float* __restrict__ S)
{
    int h = blockIdx.z;
    const float* A = Q + h * HDIM;
    const float* B = Kk + h * HDIM;
    float* C = S + (size_t)h * TT * TT;
    __shared__ float As[16][64];
    __shared__ float Bs[16][64];
    int bm = blockIdx.y * 64, bn = blockIdx.x * 64;
    int tid = threadIdx.x;
    int lr = tid >> 2, lc = tid & 3;
    int ty = tid >> 4, tx = tid & 15;
    float acc[4][4];
#pragma unroll
    for (int i = 0; i < 4; i++)
#pragma unroll
        for (int j = 0; j < 4; j++) acc[i][j] = 0.f;
    for (int k0 = 0; k0 < HDIM; k0 += 16) {
        float4 a4 = *(const float4*)(A + (size_t)(bm + lr) * DD + k0 + lc * 4);
        float4 b4 = *(const float4*)(B + (size_t)(bn + lr) * DD + k0 + lc * 4);
        As[lc*4+0][lr] = a4.x; As[lc*4+1][lr] = a4.y; As[lc*4+2][lr] = a4.z; As[lc*4+3][lr] = a4.w;
        Bs[lc*4+0][lr] = b4.x; Bs[lc*4+1][lr] = b4.y; Bs[lc*4+2][lr] = b4.z; Bs[lc*4+3][lr] = b4.w;
        __syncthreads();
#pragma unroll
        for (int kk = 0; kk < 16; kk++) {
            float4 av = *(const float4*)&As[kk][ty*4];
            float4 bv = *(const float4*)&Bs[kk][tx*4];
            float ar[4] = {av.x, av.y, av.z, av.w};
            float br[4] = {bv.x, bv.y, bv.z, bv.w};
#pragma unroll
            for (int i = 0; i < 4; i++)
#pragma unroll
                for (int j = 0; j < 4; j++) acc[i][j] += ar[i] * br[j];
        }
        __syncthreads();
    }
#pragma unroll
    for (int i = 0; i < 4; i++) {
        int row = bm + ty*4 + i;
#pragma unroll
        for (int j = 0; j < 4; j++) {
            int col = bn + tx*4 + j;
            float v = acc[i][j] * ASCALE;
            if (col > row) v = NEGINF;
            C[(size_t)row * TT + col] = v;
        }
    }
}

__global__ void pv_gemm(const float* __restrict__ P, const float* __restrict__ V,
                        float* __restrict__ CTX)
{
    int h = blockIdx.z;
    const float* A = P + (size_t)h * TT * TT;
    const float* B = V + h * HDIM;
    float* C = CTX + h * HDIM;
    __shared__ float As[16][64];
    __shared__ float Bs[16][64];
    int bm = blockIdx.y * 64, bn = blockIdx.x * 64;
    int tid = threadIdx.x;
    int lr = tid >> 2, lc = tid & 3;
    int ty = tid >> 4, tx = tid & 15;
    float acc[4][4];
#pragma unroll
    for (int i = 0; i < 4; i++)
#pragma unroll
        for (int j = 0; j < 4; j++) acc[i][j] = 0.f;
    for (int k0 = 0; k0 < TT; k0 += 16) {
        float4 a4 = *(const float4*)(A + (size_t)(bm + lr) * TT + k0 + lc * 4);
        As[lc*4+0][lr] = a4.x; As[lc*4+1][lr] = a4.y; As[lc*4+2][lr] = a4.z; As[lc*4+3][lr] = a4.w;
#pragma unroll
        for (int i = 0; i < 4; i++) {
            int kr = i * 4 + (tid >> 6);
            Bs[kr][tid & 63] = B[(size_t)(k0 + kr) * DD + bn + (tid & 63)];
        }
        __syncthreads();
#pragma unroll
        for (int kk = 0; kk < 16; kk++) {
            float4 av = *(const float4*)&As[kk][ty*4];
            float4 bv = *(const float4*)&Bs[kk][tx*4];
            float ar[4] = {av.x, av.y, av.z, av.w};
            float br[4] = {bv.x, bv.y, bv.z, bv.w};
#pragma unroll
            for (int i = 0; i < 4; i++)
#pragma unroll
                for (int j = 0; j < 4; j++) acc[i][j] += ar[i] * br[j];
        }
        __syncthreads();
    }
#pragma unroll
    for (int i = 0; i < 4; i++) {
        int row = bm + ty*4 + i;
#pragma unroll
        for (int j = 0; j < 4; j++)
            C[(size_t)row * DD + bn + tx*4 + j] = acc[i][j];
    }
}

// ==================== bf16x3 tensor-core dense NT GEMM ====================
// C[bm:bm+64, bn:bn+128] = A[64,2048] @ B[128 rows,2048]^T  (+res, dual-store)
__device__ __forceinline__ void dense_bf16x3(
    const float* __restrict__ A, const float* __restrict__ B,
    float* __restrict__ C, const float* __restrict__ res, float* __restrict__ C2)
{
    __shared__ __align__(16) __nv_bfloat16 sA[2][2][64][LW];
    __shared__ __align__(16) __nv_bfloat16 sB[2][2][128][LW];
    const int tid = threadIdx.x;
    const int lane = tid & 31, wid = tid >> 5;
    const int wm = wid & 3, wn = wid >> 2;       // warp grid 4m x 2n, warp tile 16x64
    const int gid = lane >> 2, tig = lane & 3;
    const int bm = blockIdx.y * 64, bn = blockIdx.x * 128;

    const int ar = tid >> 2, aq = tid & 3;       // A: 64 rows x 4 quads, 1 per thread
    const float* gA  = A + (size_t)(bm + ar) * DD + aq * 4;
    const float* gB0 = B + (size_t)(bn + ar) * DD + aq * 4;        // rows 0..63
    const float* gB1 = B + (size_t)(bn + ar + 64) * DD + aq * 4;   // rows 64..127

    const unsigned baseAh = smem_u32(&sA[0][0][0][0]);
    const unsigned baseAl = smem_u32(&sA[0][1][0][0]);
    const unsigned baseBh = smem_u32(&sB[0][0][0][0]);
    const unsigned baseBl = smem_u32(&sB[0][1][0][0]);
    const unsigned stageA = 2u * 64 * LWB;
    const unsigned stageB = 2u * 128 * LWB;
    const int aRow = wm * 16 + (lane & 15);
    const int aColB = ((lane >> 4) & 1) * 16;
    const unsigned aOffH = baseAh + aRow * LWB + aColB;
    const unsigned aOffL = baseAl + aRow * LWB + aColB;
    const int bRow = wn * 64 + (lane & 7) + ((lane >> 4) & 1) * 8;
    const int bColB = ((lane >> 3) & 1) * 16;
    const unsigned bOffH = baseBh + bRow * LWB + bColB;
    const unsigned bOffL = baseBl + bRow * LWB + bColB;

    float acc[8][4];
#pragma unroll
    for (int t = 0; t < 8; t++)
#pragma unroll
        for (int j = 0; j < 4; j++) acc[t][j] = 0.f;

    // prologue
    float4 a4  = *(const float4*)gA;
    float4 b40 = *(const float4*)gB0;
    float4 b41 = *(const float4*)gB1;
    cvt_store(a4,  &sA[0][0][ar][aq*4],    &sA[0][1][ar][aq*4]);
    cvt_store(b40, &sB[0][0][ar][aq*4],    &sB[0][1][ar][aq*4]);
    cvt_store(b41, &sB[0][0][ar+64][aq*4], &sB[0][1][ar+64][aq*4]);
    __syncthreads();

    const int NIT = DD / 16;
    for (int it = 0; it < NIT; it++) {
        const int cur = it & 1;
        const bool nx = (it + 1 < NIT);
        if (nx) {
            const int k0 = (it + 1) * 16;
            a4  = *(const float4*)(gA + k0);
            b40 = *(const float4*)(gB0 + k0);
            b41 = *(const float4*)(gB1 + k0);
        }
        const unsigned soA = cur * stageA;
        const unsigned soB = cur * stageB;
        unsigned ah0,ah1,ah2,ah3, al0,al1,al2,al3;
        ldmat_x4(aOffH + soA, ah0, ah1, ah2, ah3);
        ldmat_x4(aOffL + soA, al0, al1, al2, al3);
#pragma unroll
        for (int p = 0; p < 4; p++) {
            unsigned bh0,bh1,bh2,bh3, bl0,bl1,bl2,bl3;
            ldmat_x4(bOffH + soB + p * 16 * LWB, bh0, bh1, bh2, bh3);
            ldmat_x4(bOffL + soB + p * 16 * LWB, bl0, bl1, bl2, bl3);
            mma_bf16(acc[2*p],   ah0,ah1,ah2,ah3, bh0,bh1);
            mma_bf16(acc[2*p+1], ah0,ah1,ah2,ah3, bh2,bh3);
            mma_bf16(acc[2*p],   ah0,ah1,ah2,ah3, bl0,bl1);
            mma_bf16(acc[2*p+1], ah0,ah1,ah2,ah3, bl2,bl3);
            mma_bf16(acc[2*p],   al0,al1,al2,al3, bh0,bh1);
            mma_bf16(acc[2*p+1], al0,al1,al2,al3, bh2,bh3);
        }
        if (nx) {
            const int ns = cur ^ 1;
            cvt_store(a4,  &sA[ns][0][ar][aq*4],    &sA[ns][1][ar][aq*4]);
            cvt_store(b40, &sB[ns][0][ar][aq*4],    &sB[ns][1][ar][aq*4]);
            cvt_store(b41, &sB[ns][0][ar+64][aq*4], &sB[ns][1][ar+64][aq*4]);
        }
        __syncthreads();
    }

#pragma unroll
    for (int t = 0; t < 8; t++) {
        const int col = bn + wn * 64 + t * 8 + tig * 2;
        const int r0 = bm + wm * 16 + gid, r1 = r0 + 8;
        float2 v0 = make_float2(acc[t][0], acc[t][1]);
        float2 v1 = make_float2(acc[t][2], acc[t][3]);
        if (res) {
            float2 e0 = *(const float2*)&res[(size_t)r0 * DD + col];
            float2 e1 = *(const float2*)&res[(size_t)r1 * DD + col];
            v0.x += e0.x; v0.y += e0.y; v1.x += e1.x; v1.y += e1.y;
        }
        *(float2*)&C[(size_t)r0 * DD + col] = v0;
        *(float2*)&C[(size_t)r1 * DD + col] = v1;
        if (C2) {
            *(float2*)&C2[(size_t)r0 * DD + col] = v0;
            *(float2*)&C2[(size_t)r1 * DD + col] = v1;
        }
    }
}

__global__ void qkv_tc_kernel(const float* __restrict__ xn,
                              const float* __restrict__ qw, const float* __restrict__ kw,
                              const float* __restrict__ vw,
                              float* __restrict__ qb, float* __restrict__ kb,
                              float* __restrict__ vb)
{
    const float* B; float* C;
    if (blockIdx.z == 0)      { B = qw; C = qb; }
    else if (blockIdx.z == 1) { B = kw; C = kb; }
    else                      { B = vw; C = vb; }
    dense_bf16x3(xn, B, C, nullptr, nullptr);
}

__global__ void oproj_tc_kernel(const float* __restrict__ ctx, const float* __restrict__ ow,
                                const float* __restrict__ x, float* __restrict__ x2,
                                float* __restrict__ out)
{
    dense_bf16x3(ctx, ow, x2, x, out);
}

// ==================== bf16x3 MoE gate_up ====================
// Per expert: act[token, n0:n0+64] = silu(gate)*up*w ; B tile = 64 gate rows + 64 up rows
__global__ void moe_gate_up_tc(const float* __restrict__ x3, const float* __restrict__ w_gu,
                               const int* __restrict__ cnt, const int* __restrict__ tok,
                               const float* __restrict__ wgt, float* __restrict__ act)
{
    const int e = blockIdx.z;
    const int nt = cnt[e];
    const int m0 = blockIdx.y * 32;
    if (m0 >= nt) return;
    const int n0 = blockIdx.x * 64;

    __shared__ __align__(16) __nv_bfloat16 sA[2][2][32][LW];
    __shared__ __align__(16) __nv_bfloat16 sB[2][2][128][LW];
    __shared__ int   stok[32];
    __shared__ float sw[32];
    float* Cs = (float*)&sB[0][0][0][0];   // 32x132 fp32 = 16896B <= 24576B, aliased post-mma

    const int tid = threadIdx.x, lane = tid & 31, wid = tid >> 5;
    const int wm = wid & 1, wn = wid >> 1;    // 2m x 4n, warp tile 16x32
    const int gid = lane >> 2, tig = lane & 3;

    if (tid < 32) {
        int rr = min(m0 + tid, nt - 1);
        stok[tid] = tok[e * 256 + rr];
        sw[tid]   = wgt[e * 256 + rr];
    }
    __syncthreads();

    const int ar = tid >> 2, aq = tid & 3;
    const float* gA = x3 + (size_t)stok[(tid < 128) ? ar : 0] * DD + aq * 4;
    const float* Wg = w_gu + (size_t)e * (2 * DFF) * DD;
    const float* gB0 = Wg + (size_t)(n0 + ar) * DD + aq * 4;          // gate rows -> sB 0..63
    const float* gB1 = Wg + (size_t)(DFF + n0 + ar) * DD + aq * 4;    // up rows   -> sB 64..127

    const unsigned baseAh = smem_u32(&sA[0][0][0][0]);
    const unsigned baseAl = smem_u32(&sA[0][1][0][0]);
    const unsigned baseBh = smem_u32(&sB[0][0][0][0]);
    const unsigned baseBl = smem_u32(&sB[0][1][0][0]);
    const unsigned stageA = 2u * 32 * LWB;
    const unsigned stageB = 2u * 128 * LWB;
    const int aRow = wm * 16 + (lane & 15);
    const int aColB = ((lane >> 4) & 1) * 16;
    const unsigned aOffH = baseAh + aRow * LWB + aColB;
    const unsigned aOffL = baseAl + aRow * LWB + aColB;
    const int bRow = wn * 32 + (lane & 7) + ((lane >> 4) & 1) * 8;
    const int bColB = ((lane >> 3) & 1) * 16;
    const unsigned bOffH = baseBh + bRow * LWB + bColB;
    const unsigned bOffL = baseBl + bRow * LWB + bColB;

    float acc[4][4];
#pragma unroll
    for (int t = 0; t < 4; t++)
#pragma unroll
        for (int j = 0; j < 4; j++) acc[t][j] = 0.f;

    float4 a4 = make_float4(0.f,0.f,0.f,0.f), b40, b41;
    if (tid < 128) a4 = *(const float4*)gA;
    b40 = *(const float4*)gB0;
    b41 = *(const float4*)gB1;
    if (tid < 128) cvt_store(a4, &sA[0][0][ar][aq*4], &sA[0][1][ar][aq*4]);
    cvt_store(b40, &sB[0][0][ar][aq*4],    &sB[0][1][ar][aq*4]);
    cvt_store(b41, &sB[0][0][ar+64][aq*4], &sB[0][1][ar+64][aq*4]);
    __syncthreads();

    const int NIT = DD / 16;
    for (int it = 0; it < NIT; it++) {
        const int cur = it & 1;
        const bool nx = (it + 1 < NIT);
        if (nx) {
            const int k0 = (it + 1) * 16;
            if (tid < 128) a4 = *(const float4*)(gA + k0);
            b40 = *(const float4*)(gB0 + k0);
            b41 = *(const float4*)(gB1 + k0);
        }
        const unsigned soA = cur * stageA;
        const unsigned soB = cur * stageB;
        unsigned ah0,ah1,ah2,ah3, al0,al1,al2,al3;
        ldmat_x4(aOffH + soA, ah0, ah1, ah2, ah3);
        ldmat_x4(aOffL + soA, al0, al1, al2, al3);
#pragma unroll
        for (int p = 0; p < 2; p++) {
            unsigned bh0,bh1,bh2,bh3, bl0,bl1,bl2,bl3;
            ldmat_x4(bOffH + soB + p * 16 * LWB, bh0, bh1, bh2, bh3);
            ldmat_x4(bOffL + soB + p * 16 * LWB, bl0, bl1, bl2, bl3);
            mma_bf16(acc[2*p],   ah0,ah1,ah2,ah3, bh0,bh1);
            mma_bf16(acc[2*p+1], ah0,ah1,ah2,ah3, bh2,bh3);
            mma_bf16(acc[2*p],   ah0,ah1,ah2,ah3, bl0,bl1);
            mma_bf16(acc[2*p+1], ah0,ah1,ah2,ah3, bl2,bl3);
            mma_bf16(acc[2*p],   al0,al1,al2,al3, bh0,bh1);
            mma_bf16(acc[2*p+1], al0,al1,al2,al3, bh2,bh3);
        }
        if (nx) {
            const int ns = cur ^ 1;
            if (tid < 128) cvt_store(a4, &sA[ns][0][ar][aq*4], &sA[ns][1][ar][aq*4]);
            cvt_store(b40, &sB[ns][0][ar][aq*4],    &sB[ns][1][ar][aq*4]);
            cvt_store(b41, &sB[ns][0][ar+64][aq*4], &sB[ns][1][ar+64][aq*4]);
        }
        __syncthreads();
    }

    // stage accumulators to shared (gate cols 0..63, up cols 64..127), then combine
#pragma unroll
    for (int t = 0; t < 4; t++) {
        const int c = wn * 32 + t * 8 + tig * 2;
        const int r0 = wm * 16 + gid;
        Cs[r0 * 132 + c]       = acc[t][0];
        Cs[r0 * 132 + c + 1]   = acc[t][1];
        Cs[(r0+8) * 132 + c]   = acc[t][2];
        Cs[(r0+8) * 132 + c+1] = acc[t][3];
    }
    __syncthreads();

    const int m = tid >> 3;
    if (m0 + m < nt) {
        const float w = sw[m];
        const int j0 = (tid & 7) * 8;
        const size_t base = ((size_t)(e * 256 + m0 + m)) * DFF + n0 + j0;
#pragma unroll
        for (int j = 0; j < 8; j++) {
            float g = Cs[m * 132 + j0 + j];
            float u = Cs[m * 132 + 64 + j0 + j];
            float sg = g / (1.f + expf(-g));
            act[base + j] = sg * u * w;
        }
    }
}

// ==================== bf16x3 MoE down-proj ====================
__global__ void moe_down_tc(const float* __restrict__ act, const float* __restrict__ w_down,
                            const int* __restrict__ cnt, const int* __restrict__ tok,
                            float* __restrict__ out)
{
    const int e = blockIdx.z;
    const int nt = cnt[e];
    const int m0 = blockIdx.y * 32;
    if (m0 >= nt) return;
    const int n0 = blockIdx.x * 128;

    __shared__ __align__(16) __nv_bfloat16 sA[2][2][32][LW];
    __shared__ __align__(16) __nv_bfloat16 sB[2][2][128][LW];
    __shared__ int stok[32];

    const int tid = threadIdx.x, lane = tid & 31, wid = tid >> 5;
    const int wm = wid & 1, wn = wid >> 1;
    const int gid = lane >> 2, tig = lane & 3;

    if (tid < 32) stok[tid] = (m0 + tid < nt) ? tok[e * 256 + m0 + tid] : 0;
    __syncthreads();

    const int ar = tid >> 2, aq = tid & 3;
    const float* gA = act + ((size_t)(e * 256 + m0 + ((tid < 128) ? ar : 0))) * DFF + aq * 4;
    const float* W = w_down + (size_t)e * DD * DFF;
    const float* gB0 = W + (size_t)(n0 + ar) * DFF + aq * 4;
    const float* gB1 = W + (size_t)(n0 + ar + 64) * DFF + aq * 4;

    const unsigned baseAh = smem_u32(&sA[0][0][0][0]);
    const unsigned baseAl = smem_u32(&sA[0][1][0][0]);
    const unsigned baseBh = smem_u32(&sB[0][0][0][0]);
    const unsigned baseBl = smem_u32(&sB[0][1][0][0]);
    const unsigned stageA = 2u * 32 * LWB;
    const unsigned stageB = 2u * 128 * LWB;
    const int aRow = wm * 16 + (lane & 15);
    const int aColB = ((lane >> 4) & 1) * 16;
    const unsigned aOffH = baseAh + aRow * LWB + aColB;
    const unsigned aOffL = baseAl + aRow * LWB + aColB;
    const int bRow = wn * 32 + (lane & 7) + ((lane >> 4) & 1) * 8;
    const int bColB = ((lane >> 3) & 1) * 16;
    const unsigned bOffH = baseBh + bRow * LWB + bColB;
    const unsigned bOffL = baseBl + bRow * LWB + bColB;

    float acc[4][4];
#pragma unroll
    for (int t = 0; t < 4; t++)
#pragma unroll
        for (int j = 0; j < 4; j++) acc[t][j] = 0.f;

    float4 a4 = make_float4(0.f,0.f,0.f,0.f), b40, b41;
    if (tid < 128) a4 = *(const float4*)gA;
    b40 = *(const float4*)gB0;
    b41 = *(const float4*)gB1;
    if (tid < 128) cvt_store(a4, &sA[0][0][ar][aq*4], &sA[0][1][ar][aq*4]);
    cvt_store(b40, &sB[0][0][ar][aq*4],    &sB[0][1][ar][aq*4]);
    cvt_store(b41, &sB[0][0][ar+64][aq*4], &sB[0][1][ar+64][aq*4]);
    __syncthreads();

    const int NIT = DFF / 16;
    for (int it = 0; it < NIT; it++) {
        const int cur = it & 1;
        const bool nx = (it + 1 < NIT);
        if (nx) {
            const int k0 = (it + 1) * 16;
            if (tid < 128) a4 = *(const float4*)(gA + k0);
            b40 = *(const float4*)(gB0 + k0);
            b41 = *(const float4*)(gB1 + k0);
        }
        const unsigned soA = cur * stageA;
        const unsigned soB = cur * stageB;
        unsigned ah0,ah1,ah2,ah3, al0,al1,al2,al3;
        ldmat_x4(aOffH + soA, ah0, ah1, ah2, ah3);
        ldmat_x4(aOffL + soA, al0, al1, al2, al3);
#pragma unroll
        for (int p = 0; p < 2; p++) {
            unsigned bh0,bh1,bh2,bh3, bl0,bl1,bl2,bl3;
            ldmat_x4(bOffH + soB + p * 16 * LWB, bh0, bh1, bh2, bh3);
            ldmat_x4(bOffL + soB + p * 16 * LWB, bl0, bl1, bl2, bl3);
            mma_bf16(acc[2*p],   ah0,ah1,ah2,ah3, bh0,bh1);
            mma_bf16(acc[2*p+1], ah0,ah1,ah2,ah3, bh2,bh3);
            mma_bf16(acc[2*p],   ah0,ah1,ah2,ah3, bl0,bl1);
            mma_bf16(acc[2*p+1], ah0,ah1,ah2,ah3, bl2,bl3);
            mma_bf16(acc[2*p],   al0,al1,al2,al3, bh0,bh1);
            mma_bf16(acc[2*p+1], al0,al1,al2,al3, bh2,bh3);
        }
        if (nx) {
            const int ns = cur ^ 1;
            if (tid < 128) cvt_store(a4, &sA[ns][0][ar][aq*4], &sA[ns][1][ar][aq*4]);
            cvt_store(b40, &sB[ns][0][ar][aq*4],    &sB[ns][1][ar][aq*4]);
            cvt_store(b41, &sB[ns][0][ar+64][aq*4], &sB[ns][1][ar+64][aq*4]);
        }
        __syncthreads();
    }

#pragma unroll
    for (int t = 0; t < 4; t++) {
        const int col = n0 + wn * 32 + t * 8 + tig * 2;
        const int r0 = wm * 16 + gid, r1 = r0 + 8;
        if (m0 + r0 < nt) {
            const int tk = stok[r0];
            atomicAdd(&out[(size_t)tk * DD + col],     acc[t][0]);
            atomicAdd(&out[(size_t)tk * DD + col + 1], acc[t][1]);
        }
        if (m0 + r1 < nt) {
            const int tk = stok[r1];
            atomicAdd(&out[(size_t)tk * DD + col],     acc[t][2]);
            atomicAdd(&out[(size_t)tk * DD + col + 1], acc[t][3]);
        }
    }
}

// ==================== host launch ====================
extern "C" void kernel_launch(void* const* d_in, const int* in_sizes, int n_in,
                              void* d_out, int out_size)
{
    const float* x    = (const float*)d_in[0];
    const float* ln1  = (const float*)d_in[1];
    const float* qw   = (const float*)d_in[2];
    const float* kw   = (const float*)d_in[3];
    const float* vw   = (const float*)d_in[4];
    const float* qn   = (const float*)d_in[5];
    const float* kn   = (const float*)d_in[6];
    const float* ow   = (const float*)d_in[7];
    const float* ln2  = (const float*)d_in[8];
    const float* gw   = (const float*)d_in[9];
    const float* guw  = (const float*)d_in[10];
    const float* dw   = (const float*)d_in[11];
    float* out = (float*)d_out;

    float *p_xn, *p_qb, *p_kb, *p_vb, *p_sc, *p_ctx, *p_x2, *p_x3, *p_act, *p_wgt;
    int *p_cnt, *p_tok;
    cudaGetSymbolAddress((void**)&p_xn,  g_xn);
    cudaGetSymbolAddress((void**)&p_qb,  g_qb);
    cudaGetSymbolAddress((void**)&p_kb,  g_kb);
    cudaGetSymbolAddress((void**)&p_vb,  g_vb);
    cudaGetSymbolAddress((void**)&p_sc,  g_sc);
    cudaGetSymbolAddress((void**)&p_ctx, g_ctx);
    cudaGetSymbolAddress((void**)&p_x2,  g_x2);
    cudaGetSymbolAddress((void**)&p_x3,  g_x3);
    cudaGetSymbolAddress((void**)&p_act, g_act);
    cudaGetSymbolAddress((void**)&p_cnt, g_cnt);
    cudaGetSymbolAddress((void**)&p_tok, g_tok);
    cudaGetSymbolAddress((void**)&p_wgt, g_wgt);

    // 1. xn = rms(x, ln1)
    rms_kernel<<<TT, 256>>>(x, ln1, p_xn);

    // 2. q/k/v projections (tensor, bf16x3)
    dim3 gqkv(DD / 128, TT / 64, 3);
    qkv_tc_kernel<<<gqkv, 256>>>(p_xn, qw, kw, vw, p_qb, p_kb, p_vb);

    // 3. q/k RMS
    rms_kernel<<<TT, 256>>>(p_qb, qn, p_qb);
    rms_kernel<<<TT, 256>>>(p_kb, kn, p_kb);

    // 4. RoPE
    rope_kernel<<<TT * NH, 64>>>(p_qb, p_kb);

    // 5. scores (fp32 SIMT) + causal
    dim3 gsc(TT / 64, TT / 64, NH);
    score_gemm<<<gsc, 256>>>(p_qb, p_kb, p_sc);

    // 6. softmax
    softmax_kernel<<<NH * TT, 256>>>(p_sc);

    // 7. ctx = P @ V (fp32 SIMT)
    dim3 gpv(HDIM / 64, TT / 64, NH);
    pv_gemm<<<gpv, 256>>>(p_sc, p_vb, p_ctx);

    // 8. x2 = x + ctx @ ow^T (tensor), dual-store into out
    dim3 go(DD / 128, TT / 64, 1);
    oproj_tc_kernel<<<go, 256>>>(p_ctx, ow, x, p_x2, out);

    // 9. x3 = rms(x2, ln2)
    rms_kernel<<<TT, 256>>>(p_x2, ln2, p_x3);

    // 10. router
    zero_cnt_kernel<<<1, 64>>>(p_cnt);
    router_kernel<<<TT, 256>>>(p_x3, gw, p_cnt, p_tok, p_wgt);

    // 11. MoE gate_up (tensor)
    dim3 ggu(DFF / 64, 8, NE);
    moe_gate_up_tc<<<ggu, 256>>>(p_x3, guw, p_cnt, p_tok, p_wgt, p_act);

    // 12. MoE down (tensor, atomic accumulate)
    dim3 gdn(DD / 128, 8, NE);
    moe_down_tc<<<gdn, 256>>>(p_act, dw, p_cnt, p_tok, out);
}